// round 3
// baseline (speedup 1.0000x reference)
#include <cuda_runtime.h>
#include <cstdint>

#define F1 128
#define F2 64
#define MAX_NODES 100000

// Scratch (device globals: allocation-free per harness rules).
// g_y: x@W1 [N,128], later reused as z = relu(h+b1)@W2 [N,64]
// g_h: spmm1 accumulator [N,128]
__device__ float g_y[(size_t)MAX_NODES * F1];
__device__ float g_h[(size_t)MAX_NODES * F1];

// ---------------------------------------------------------------------------
// init: zero h accumulator, seed out with b2 broadcast
// ---------------------------------------------------------------------------
__global__ __launch_bounds__(256) void init_kernel(float* __restrict__ out,
                                                   const float* __restrict__ b2,
                                                   int n_nodes) {
    int i = blockIdx.x * 256 + threadIdx.x;
    if (i < n_nodes * F1) g_h[i] = 0.0f;
    if (i < n_nodes * F2) out[i] = __ldg(b2 + (i & (F2 - 1)));
}

// ---------------------------------------------------------------------------
// GEMM: Y[n_rows, N] = A'[n_rows, K] @ W[K, N]
// A' = A  (RELU_BIAS=false)  or  A' = relu(A + bias[k]) (RELU_BIAS=true)
// Tile: 64 rows x N cols, 256 threads, KC=16 k-chunks in smem.
// ---------------------------------------------------------------------------
template <int K, int N, bool RELU_BIAS>
__global__ __launch_bounds__(256) void gemm_kernel(const float* __restrict__ A,
                                                   const float* __restrict__ W,
                                                   const float* __restrict__ bias,
                                                   float* __restrict__ Y,
                                                   int n_rows) {
    constexpr int KC = 16;
    constexpr int CT = N / 4;          // threads across cols (each does float4)
    constexpr int GROUPS = 256 / CT;   // row groups
    constexpr int RT = 64 / GROUPS;    // rows per thread

    __shared__ float As[KC][64 + 1];
    __shared__ float Ws[KC][N];

    const int t = threadIdx.x;
    const int row0 = blockIdx.x * 64;
    const int tc = t % CT;
    const int tg = t / CT;

    float acc[RT][4];
#pragma unroll
    for (int r = 0; r < RT; r++) {
        acc[r][0] = 0.f; acc[r][1] = 0.f; acc[r][2] = 0.f; acc[r][3] = 0.f;
    }

    for (int k0 = 0; k0 < K; k0 += KC) {
        // --- load A tile (64 rows x 16 k), transposed into As[k][row] ---
        {
            const int r = t >> 2;              // 0..63
            const int kq = (t & 3) * 4;        // 0,4,8,12
            const int grow = row0 + r;
            float4 av = make_float4(0.f, 0.f, 0.f, 0.f);
            if (grow < n_rows)
                av = *reinterpret_cast<const float4*>(A + (size_t)grow * K + k0 + kq);
            if (RELU_BIAS) {
                float4 bv = *reinterpret_cast<const float4*>(bias + k0 + kq);
                av.x = fmaxf(av.x + bv.x, 0.f);
                av.y = fmaxf(av.y + bv.y, 0.f);
                av.z = fmaxf(av.z + bv.z, 0.f);
                av.w = fmaxf(av.w + bv.w, 0.f);
            }
            As[kq + 0][r] = av.x;
            As[kq + 1][r] = av.y;
            As[kq + 2][r] = av.z;
            As[kq + 3][r] = av.w;
        }
        // --- load W tile (16 x N) ---
        {
            constexpr int VEC = KC * N / 4;    // float4 count (512 or 256)
#pragma unroll
            for (int j = 0; j < VEC / 256; j++) {
                int idx = t + 256 * j;
                int kk = idx / (N / 4);
                int nq = idx % (N / 4);
                *reinterpret_cast<float4*>(&Ws[kk][nq * 4]) =
                    *reinterpret_cast<const float4*>(W + (size_t)(k0 + kk) * N + nq * 4);
            }
        }
        __syncthreads();

#pragma unroll
        for (int k = 0; k < KC; k++) {
            float4 wv = *reinterpret_cast<float4*>(&Ws[k][tc * 4]);
#pragma unroll
            for (int r = 0; r < RT; r++) {
                float a = As[k][tg * RT + r];
                acc[r][0] += a * wv.x;
                acc[r][1] += a * wv.y;
                acc[r][2] += a * wv.z;
                acc[r][3] += a * wv.w;
            }
        }
        __syncthreads();
    }

#pragma unroll
    for (int r = 0; r < RT; r++) {
        int grow = row0 + tg * RT + r;
        if (grow < n_rows) {
            float4 o = make_float4(acc[r][0], acc[r][1], acc[r][2], acc[r][3]);
            *reinterpret_cast<float4*>(Y + (size_t)grow * N + tc * 4) = o;
        }
    }
}

// ---------------------------------------------------------------------------
// SPMM: dst[row] += val * src[col], warp per edge, vectorized global
// reductions (red.global.add). Contiguous per-warp edge ranges keep the
// rows/cols/vals metadata loads L1-resident; 4-edge manual unroll for MLP.
// ---------------------------------------------------------------------------
__device__ __forceinline__ void red_add_v4(float* p, float4 v) {
    asm volatile("red.global.add.v4.f32 [%0], {%1, %2, %3, %4};" ::"l"(p),
                 "f"(v.x), "f"(v.y), "f"(v.z), "f"(v.w)
                 : "memory");
}
__device__ __forceinline__ void red_add_v2(float* p, float2 v) {
    asm volatile("red.global.add.v2.f32 [%0], {%1, %2};" ::"l"(p), "f"(v.x), "f"(v.y)
                 : "memory");
}

__global__ __launch_bounds__(256) void spmm128_kernel(const int* __restrict__ rows,
                                                      const int* __restrict__ cols,
                                                      const float* __restrict__ vals,
                                                      const float* __restrict__ src,
                                                      float* __restrict__ dst,
                                                      int n_edges) {
    const int lane = threadIdx.x & 31;
    const int warp = (blockIdx.x * blockDim.x + threadIdx.x) >> 5;
    const int nwarps = (gridDim.x * blockDim.x) >> 5;
    const int per = (n_edges + nwarps - 1) / nwarps;
    const int start = warp * per;
    const int end = min(start + per, n_edges);

    int e = start;
    for (; e + 4 <= end; e += 4) {
        int r[4], c[4];
        float v[4];
#pragma unroll
        for (int j = 0; j < 4; j++) {
            r[j] = __ldg(rows + e + j);
            c[j] = __ldg(cols + e + j);
            v[j] = __ldg(vals + e + j);
        }
        float4 t[4];
#pragma unroll
        for (int j = 0; j < 4; j++)
            t[j] = __ldg(reinterpret_cast<const float4*>(src + (size_t)c[j] * F1) + lane);
#pragma unroll
        for (int j = 0; j < 4; j++) {
            float4 m = make_float4(t[j].x * v[j], t[j].y * v[j], t[j].z * v[j], t[j].w * v[j]);
            red_add_v4(dst + (size_t)r[j] * F1 + lane * 4, m);
        }
    }
    for (; e < end; e++) {
        int r = __ldg(rows + e);
        int c = __ldg(cols + e);
        float v = __ldg(vals + e);
        float4 t = __ldg(reinterpret_cast<const float4*>(src + (size_t)c * F1) + lane);
        float4 m = make_float4(t.x * v, t.y * v, t.z * v, t.w * v);
        red_add_v4(dst + (size_t)r * F1 + lane * 4, m);
    }
}

__global__ __launch_bounds__(256) void spmm64_kernel(const int* __restrict__ rows,
                                                     const int* __restrict__ cols,
                                                     const float* __restrict__ vals,
                                                     const float* __restrict__ src,
                                                     float* __restrict__ dst,
                                                     int n_edges) {
    const int lane = threadIdx.x & 31;
    const int warp = (blockIdx.x * blockDim.x + threadIdx.x) >> 5;
    const int nwarps = (gridDim.x * blockDim.x) >> 5;
    const int per = (n_edges + nwarps - 1) / nwarps;
    const int start = warp * per;
    const int end = min(start + per, n_edges);

    int e = start;
    for (; e + 4 <= end; e += 4) {
        int r[4], c[4];
        float v[4];
#pragma unroll
        for (int j = 0; j < 4; j++) {
            r[j] = __ldg(rows + e + j);
            c[j] = __ldg(cols + e + j);
            v[j] = __ldg(vals + e + j);
        }
        float2 t[4];
#pragma unroll
        for (int j = 0; j < 4; j++)
            t[j] = __ldg(reinterpret_cast<const float2*>(src + (size_t)c[j] * F2) + lane);
#pragma unroll
        for (int j = 0; j < 4; j++) {
            float2 m = make_float2(t[j].x * v[j], t[j].y * v[j]);
            red_add_v2(dst + (size_t)r[j] * F2 + lane * 2, m);
        }
    }
    for (; e < end; e++) {
        int r = __ldg(rows + e);
        int c = __ldg(cols + e);
        float v = __ldg(vals + e);
        float2 t = __ldg(reinterpret_cast<const float2*>(src + (size_t)c * F2) + lane);
        float2 m = make_float2(t.x * v, t.y * v);
        red_add_v2(dst + (size_t)r * F2 + lane * 2, m);
    }
}

// ---------------------------------------------------------------------------
// launch
// ---------------------------------------------------------------------------
extern "C" void kernel_launch(void* const* d_in, const int* in_sizes, int n_in,
                              void* d_out, int out_size) {
    const float* x = (const float*)d_in[0];
    const int* adj_rows = (const int*)d_in[1];
    const int* adj_cols = (const int*)d_in[2];
    const float* adj_vals = (const float*)d_in[3];
    const float* W1 = (const float*)d_in[4];
    const float* b1 = (const float*)d_in[5];
    const float* W2 = (const float*)d_in[6];
    const float* b2 = (const float*)d_in[7];
    float* out = (float*)d_out;

    const int n_nodes = in_sizes[0] / 256;
    const int n_edges = in_sizes[1];

    void* yp_ = nullptr;
    void* hp_ = nullptr;
    cudaGetSymbolAddress(&yp_, g_y);
    cudaGetSymbolAddress(&hp_, g_h);
    float* y = (float*)yp_;
    float* h = (float*)hp_;
    float* z = y;  // reuse g_y for z after spmm1 consumed it

    // 1) init: h = 0, out = b2
    {
        int total = n_nodes * F1;
        init_kernel<<<(total + 255) / 256, 256>>>(out, b2, n_nodes);
    }
    // 2) y = x @ W1
    gemm_kernel<256, F1, false><<<(n_nodes + 63) / 64, 256>>>(x, W1, nullptr, y, n_nodes);
    // 3) h += spmm(y)
    spmm128_kernel<<<1184, 256>>>(adj_rows, adj_cols, adj_vals, y, h, n_edges);
    // 4) z = relu(h + b1) @ W2
    gemm_kernel<F1, F2, true><<<(n_nodes + 63) / 64, 256>>>(h, W2, b1, z, n_nodes);
    // 5) out += spmm(z)
    spmm64_kernel<<<1184, 256>>>(adj_rows, adj_cols, adj_vals, z, out, n_edges);
}

// round 4
// speedup vs baseline: 1.6263x; 1.6263x over previous
#include <cuda_runtime.h>
#include <cstdint>

#define F1 128
#define F2 64
#define MAX_NODES 100000
#define MAX_EDGES 3200000

// ---------------------------------------------------------------------------
// Device-global scratch (allocation-free per harness rules)
// ---------------------------------------------------------------------------
__device__ float g_y[(size_t)MAX_NODES * F1];   // x@W1, later reused for z
__device__ float g_h[(size_t)MAX_NODES * F1];   // spmm1 output
__device__ unsigned long long g_edges[MAX_EDGES]; // packed (col, val) sorted by row
__device__ int g_cnt[MAX_NODES];
__device__ int g_ptrE[MAX_NODES];               // per-block exclusive scan
__device__ int g_bsum[128];
__device__ int g_bsumE[128];
__device__ int g_ptr[MAX_NODES + 1];            // CSR row offsets
__device__ int g_work[MAX_NODES];               // scatter cursors

// ---------------------------------------------------------------------------
// CSR build: zero counts -> histogram -> 2-level exclusive scan -> scatter
// ---------------------------------------------------------------------------
__global__ __launch_bounds__(256) void zero_cnt_kernel(int n_nodes) {
    int i = blockIdx.x * 256 + threadIdx.x;
    if (i < n_nodes) g_cnt[i] = 0;
}

__global__ __launch_bounds__(256) void hist_kernel(const int* __restrict__ rows,
                                                   int n_edges) {
    int e = blockIdx.x * 256 + threadIdx.x;
    if (e < n_edges) atomicAdd(&g_cnt[__ldg(rows + e)], 1);
}

// Exclusive scan of 1024 elements per block (256 threads x 4).
__global__ __launch_bounds__(256) void scan1_kernel(int n) {
    __shared__ int s[256];
    const int t = threadIdx.x;
    const int base = blockIdx.x * 1024 + t * 4;
    int v[4];
#pragma unroll
    for (int j = 0; j < 4; j++) v[j] = (base + j < n) ? g_cnt[base + j] : 0;
    int tsum = v[0] + v[1] + v[2] + v[3];
    s[t] = tsum;
    __syncthreads();
    for (int off = 1; off < 256; off <<= 1) {
        int x = 0;
        if (t >= off) x = s[t - off];
        __syncthreads();
        if (t >= off) s[t] += x;
        __syncthreads();
    }
    int run = s[t] - tsum;  // exclusive
#pragma unroll
    for (int j = 0; j < 4; j++) {
        if (base + j < n) g_ptrE[base + j] = run;
        run += v[j];
    }
    if (t == 255) g_bsum[blockIdx.x] = s[255];
}

// Exclusive scan of the (<=512) block sums, single block.
__global__ __launch_bounds__(256) void scan2_kernel(int nb) {
    __shared__ int s[256];
    const int t = threadIdx.x;
    const int base = t * 4;
    int v[4];
#pragma unroll
    for (int j = 0; j < 4; j++) v[j] = (base + j < nb) ? g_bsum[base + j] : 0;
    int tsum = v[0] + v[1] + v[2] + v[3];
    s[t] = tsum;
    __syncthreads();
    for (int off = 1; off < 256; off <<= 1) {
        int x = 0;
        if (t >= off) x = s[t - off];
        __syncthreads();
        if (t >= off) s[t] += x;
        __syncthreads();
    }
    int run = s[t] - tsum;
#pragma unroll
    for (int j = 0; j < 4; j++) {
        if (base + j < nb) g_bsumE[base + j] = run;
        run += v[j];
    }
}

__global__ __launch_bounds__(256) void scan3_kernel(int n_nodes, int n_edges) {
    int i = blockIdx.x * 256 + threadIdx.x;
    if (i < n_nodes) {
        int p = g_ptrE[i] + g_bsumE[i >> 10];
        g_ptr[i] = p;
        g_work[i] = p;
    }
    if (i == 0) g_ptr[n_nodes] = n_edges;
}

__global__ __launch_bounds__(256) void scatter_kernel(const int* __restrict__ rows,
                                                      const int* __restrict__ cols,
                                                      const float* __restrict__ vals,
                                                      int n_edges) {
    int e = blockIdx.x * 256 + threadIdx.x;
    if (e < n_edges) {
        int r = __ldg(rows + e);
        int pos = atomicAdd(&g_work[r], 1);
        unsigned long long packed =
            (unsigned long long)(unsigned int)__ldg(cols + e) |
            ((unsigned long long)__float_as_uint(__ldg(vals + e)) << 32);
        g_edges[pos] = packed;
    }
}

// ---------------------------------------------------------------------------
// Pull-based CSR SPMM: one warp per output row, register accumulate, one store.
// ---------------------------------------------------------------------------
__global__ __launch_bounds__(256) void csr_spmm128_kernel(const float* __restrict__ src,
                                                          float* __restrict__ dst,
                                                          int n_nodes) {
    const int lane = threadIdx.x & 31;
    const int row = (blockIdx.x * 256 + threadIdx.x) >> 5;
    if (row >= n_nodes) return;
    const int p0 = __ldg(&g_ptr[row]);
    const int p1 = __ldg(&g_ptr[row + 1]);
    const float4* s4 = reinterpret_cast<const float4*>(src);

    float4 acc = make_float4(0.f, 0.f, 0.f, 0.f);
    int e = p0;
    for (; e + 2 <= p1; e += 2) {
        unsigned long long e0 = __ldg(&g_edges[e]);
        unsigned long long e1 = __ldg(&g_edges[e + 1]);
        int c0 = (int)(unsigned int)e0;
        int c1 = (int)(unsigned int)e1;
        float v0 = __uint_as_float((unsigned int)(e0 >> 32));
        float v1 = __uint_as_float((unsigned int)(e1 >> 32));
        float4 a = __ldg(s4 + (size_t)c0 * 32 + lane);
        float4 b = __ldg(s4 + (size_t)c1 * 32 + lane);
        acc.x = fmaf(a.x, v0, fmaf(b.x, v1, acc.x));
        acc.y = fmaf(a.y, v0, fmaf(b.y, v1, acc.y));
        acc.z = fmaf(a.z, v0, fmaf(b.z, v1, acc.z));
        acc.w = fmaf(a.w, v0, fmaf(b.w, v1, acc.w));
    }
    if (e < p1) {
        unsigned long long e0 = __ldg(&g_edges[e]);
        int c0 = (int)(unsigned int)e0;
        float v0 = __uint_as_float((unsigned int)(e0 >> 32));
        float4 a = __ldg(s4 + (size_t)c0 * 32 + lane);
        acc.x = fmaf(a.x, v0, acc.x);
        acc.y = fmaf(a.y, v0, acc.y);
        acc.z = fmaf(a.z, v0, acc.z);
        acc.w = fmaf(a.w, v0, acc.w);
    }
    reinterpret_cast<float4*>(dst)[(size_t)row * 32 + lane] = acc;
}

// F=64 variant with b2 epilogue: out[row] = sum + b2
__global__ __launch_bounds__(256) void csr_spmm64_kernel(const float* __restrict__ src,
                                                         const float* __restrict__ b2,
                                                         float* __restrict__ dst,
                                                         int n_nodes) {
    const int lane = threadIdx.x & 31;
    const int row = (blockIdx.x * 256 + threadIdx.x) >> 5;
    if (row >= n_nodes) return;
    const int p0 = __ldg(&g_ptr[row]);
    const int p1 = __ldg(&g_ptr[row + 1]);
    const float2* s2 = reinterpret_cast<const float2*>(src);

    float2 acc = make_float2(0.f, 0.f);
    int e = p0;
    for (; e + 2 <= p1; e += 2) {
        unsigned long long e0 = __ldg(&g_edges[e]);
        unsigned long long e1 = __ldg(&g_edges[e + 1]);
        int c0 = (int)(unsigned int)e0;
        int c1 = (int)(unsigned int)e1;
        float v0 = __uint_as_float((unsigned int)(e0 >> 32));
        float v1 = __uint_as_float((unsigned int)(e1 >> 32));
        float2 a = __ldg(s2 + (size_t)c0 * 32 + lane);
        float2 b = __ldg(s2 + (size_t)c1 * 32 + lane);
        acc.x = fmaf(a.x, v0, fmaf(b.x, v1, acc.x));
        acc.y = fmaf(a.y, v0, fmaf(b.y, v1, acc.y));
    }
    if (e < p1) {
        unsigned long long e0 = __ldg(&g_edges[e]);
        int c0 = (int)(unsigned int)e0;
        float v0 = __uint_as_float((unsigned int)(e0 >> 32));
        float2 a = __ldg(s2 + (size_t)c0 * 32 + lane);
        acc.x = fmaf(a.x, v0, acc.x);
        acc.y = fmaf(a.y, v0, acc.y);
    }
    float2 bv = __ldg(reinterpret_cast<const float2*>(b2) + lane);
    acc.x += bv.x;
    acc.y += bv.y;
    reinterpret_cast<float2*>(dst)[(size_t)row * 32 + lane] = acc;
}

// ---------------------------------------------------------------------------
// GEMM: Y[n_rows, N] = A'[n_rows, K] @ W[K, N]   (A' = relu(A+bias) optionally)
// ---------------------------------------------------------------------------
template <int K, int N, bool RELU_BIAS>
__global__ __launch_bounds__(256) void gemm_kernel(const float* __restrict__ A,
                                                   const float* __restrict__ W,
                                                   const float* __restrict__ bias,
                                                   float* __restrict__ Y,
                                                   int n_rows) {
    constexpr int KC = 16;
    constexpr int CT = N / 4;
    constexpr int GROUPS = 256 / CT;
    constexpr int RT = 64 / GROUPS;

    __shared__ float As[KC][64 + 1];
    __shared__ float Ws[KC][N];

    const int t = threadIdx.x;
    const int row0 = blockIdx.x * 64;
    const int tc = t % CT;
    const int tg = t / CT;

    float acc[RT][4];
#pragma unroll
    for (int r = 0; r < RT; r++) {
        acc[r][0] = 0.f; acc[r][1] = 0.f; acc[r][2] = 0.f; acc[r][3] = 0.f;
    }

    for (int k0 = 0; k0 < K; k0 += KC) {
        {
            const int r = t >> 2;
            const int kq = (t & 3) * 4;
            const int grow = row0 + r;
            float4 av = make_float4(0.f, 0.f, 0.f, 0.f);
            if (grow < n_rows)
                av = *reinterpret_cast<const float4*>(A + (size_t)grow * K + k0 + kq);
            if (RELU_BIAS) {
                float4 bv = *reinterpret_cast<const float4*>(bias + k0 + kq);
                av.x = fmaxf(av.x + bv.x, 0.f);
                av.y = fmaxf(av.y + bv.y, 0.f);
                av.z = fmaxf(av.z + bv.z, 0.f);
                av.w = fmaxf(av.w + bv.w, 0.f);
            }
            As[kq + 0][r] = av.x;
            As[kq + 1][r] = av.y;
            As[kq + 2][r] = av.z;
            As[kq + 3][r] = av.w;
        }
        {
            constexpr int VEC = KC * N / 4;
#pragma unroll
            for (int j = 0; j < VEC / 256; j++) {
                int idx = t + 256 * j;
                int kk = idx / (N / 4);
                int nq = idx % (N / 4);
                *reinterpret_cast<float4*>(&Ws[kk][nq * 4]) =
                    *reinterpret_cast<const float4*>(W + (size_t)(k0 + kk) * N + nq * 4);
            }
        }
        __syncthreads();

#pragma unroll
        for (int k = 0; k < KC; k++) {
            float4 wv = *reinterpret_cast<float4*>(&Ws[k][tc * 4]);
#pragma unroll
            for (int r = 0; r < RT; r++) {
                float a = As[k][tg * RT + r];
                acc[r][0] += a * wv.x;
                acc[r][1] += a * wv.y;
                acc[r][2] += a * wv.z;
                acc[r][3] += a * wv.w;
            }
        }
        __syncthreads();
    }

#pragma unroll
    for (int r = 0; r < RT; r++) {
        int grow = row0 + tg * RT + r;
        if (grow < n_rows) {
            float4 o = make_float4(acc[r][0], acc[r][1], acc[r][2], acc[r][3]);
            *reinterpret_cast<float4*>(Y + (size_t)grow * N + tc * 4) = o;
        }
    }
}

// ---------------------------------------------------------------------------
// launch
// ---------------------------------------------------------------------------
extern "C" void kernel_launch(void* const* d_in, const int* in_sizes, int n_in,
                              void* d_out, int out_size) {
    const float* x = (const float*)d_in[0];
    const int* adj_rows = (const int*)d_in[1];
    const int* adj_cols = (const int*)d_in[2];
    const float* adj_vals = (const float*)d_in[3];
    const float* W1 = (const float*)d_in[4];
    const float* b1 = (const float*)d_in[5];
    const float* W2 = (const float*)d_in[6];
    const float* b2 = (const float*)d_in[7];
    float* out = (float*)d_out;

    const int n_nodes = in_sizes[0] / 256;
    const int n_edges = in_sizes[1];

    void* yp_ = nullptr;
    void* hp_ = nullptr;
    cudaGetSymbolAddress(&yp_, g_y);
    cudaGetSymbolAddress(&hp_, g_h);
    float* y = (float*)yp_;
    float* h = (float*)hp_;
    float* z = y;  // reuse g_y for z after spmm1 consumed it

    const int nb_scan = (n_nodes + 1023) / 1024;
    const int eb = (n_edges + 255) / 256;
    const int nb_nodes = (n_nodes + 255) / 256;

    // --- CSR build ---
    zero_cnt_kernel<<<nb_nodes, 256>>>(n_nodes);
    hist_kernel<<<eb, 256>>>(adj_rows, n_edges);
    scan1_kernel<<<nb_scan, 256>>>(n_nodes);
    scan2_kernel<<<1, 256>>>(nb_scan);
    scan3_kernel<<<nb_nodes + 1, 256>>>(n_nodes, n_edges);
    scatter_kernel<<<eb, 256>>>(adj_rows, adj_cols, adj_vals, n_edges);

    // --- y = x @ W1 ---
    gemm_kernel<256, F1, false><<<(n_nodes + 63) / 64, 256>>>(x, W1, nullptr, y, n_nodes);
    // --- h = spmm(y) ---
    csr_spmm128_kernel<<<(n_nodes * 32 + 255) / 256, 256>>>(y, h, n_nodes);
    // --- z = relu(h + b1) @ W2 ---
    gemm_kernel<F1, F2, true><<<(n_nodes + 63) / 64, 256>>>(h, W2, b1, z, n_nodes);
    // --- out = spmm(z) + b2 ---
    csr_spmm64_kernel<<<(n_nodes * 32 + 255) / 256, 256>>>(z, b2, out, n_nodes);
}

// round 6
// speedup vs baseline: 1.7672x; 1.0867x over previous
#include <cuda_runtime.h>
#include <cuda_fp16.h>
#include <cstdint>

#define F1 128
#define F2 64
#define MAX_NODES 100000
#define MAX_EDGES 3200000

// ---------------------------------------------------------------------------
// Device-global scratch (allocation-free per harness rules)
// g_y: fp16 x@W1 [N,128]; later reused for fp16 z [N,64]
// g_h: fp32 spmm1 output [N,128]
// ---------------------------------------------------------------------------
__device__ __half g_y[(size_t)MAX_NODES * F1];
__device__ float g_h[(size_t)MAX_NODES * F1];
__device__ unsigned long long g_edges[MAX_EDGES]; // packed (col, val) sorted by row
__device__ int g_cnt[MAX_NODES];
__device__ int g_ptrE[MAX_NODES];
__device__ int g_bsum[128];
__device__ int g_bsumE[128];
__device__ int g_ptr[MAX_NODES + 1];
__device__ int g_work[MAX_NODES];

// ---------------------------------------------------------------------------
// CSR build: zero counts -> histogram -> 2-level exclusive scan -> scatter
// ---------------------------------------------------------------------------
__global__ __launch_bounds__(256) void zero_cnt_kernel(int n_nodes) {
    int i = blockIdx.x * 256 + threadIdx.x;
    if (i < n_nodes) g_cnt[i] = 0;
}

__global__ __launch_bounds__(256) void hist_kernel(const int* __restrict__ rows,
                                                   int n_edges) {
    int e = blockIdx.x * 256 + threadIdx.x;
    if (e < n_edges) atomicAdd(&g_cnt[__ldg(rows + e)], 1);
}

__global__ __launch_bounds__(256) void scan1_kernel(int n) {
    __shared__ int s[256];
    const int t = threadIdx.x;
    const int base = blockIdx.x * 1024 + t * 4;
    int v[4];
#pragma unroll
    for (int j = 0; j < 4; j++) v[j] = (base + j < n) ? g_cnt[base + j] : 0;
    int tsum = v[0] + v[1] + v[2] + v[3];
    s[t] = tsum;
    __syncthreads();
    for (int off = 1; off < 256; off <<= 1) {
        int x = 0;
        if (t >= off) x = s[t - off];
        __syncthreads();
        if (t >= off) s[t] += x;
        __syncthreads();
    }
    int run = s[t] - tsum;
#pragma unroll
    for (int j = 0; j < 4; j++) {
        if (base + j < n) g_ptrE[base + j] = run;
        run += v[j];
    }
    if (t == 255) g_bsum[blockIdx.x] = s[255];
}

__global__ __launch_bounds__(256) void scan2_kernel(int nb) {
    __shared__ int s[256];
    const int t = threadIdx.x;
    const int base = t * 4;
    int v[4];
#pragma unroll
    for (int j = 0; j < 4; j++) v[j] = (base + j < nb) ? g_bsum[base + j] : 0;
    int tsum = v[0] + v[1] + v[2] + v[3];
    s[t] = tsum;
    __syncthreads();
    for (int off = 1; off < 256; off <<= 1) {
        int x = 0;
        if (t >= off) x = s[t - off];
        __syncthreads();
        if (t >= off) s[t] += x;
        __syncthreads();
    }
    int run = s[t] - tsum;
#pragma unroll
    for (int j = 0; j < 4; j++) {
        if (base + j < nb) g_bsumE[base + j] = run;
        run += v[j];
    }
}

__global__ __launch_bounds__(256) void scan3_kernel(int n_nodes, int n_edges) {
    int i = blockIdx.x * 256 + threadIdx.x;
    if (i < n_nodes) {
        int p = g_ptrE[i] + g_bsumE[i >> 10];
        g_ptr[i] = p;
        g_work[i] = p;
    }
    if (i == 0) g_ptr[n_nodes] = n_edges;
}

__global__ __launch_bounds__(256) void scatter_kernel(const int* __restrict__ rows,
                                                      const int* __restrict__ cols,
                                                      const float* __restrict__ vals,
                                                      int n_edges) {
    int e = blockIdx.x * 256 + threadIdx.x;
    if (e < n_edges) {
        int r = __ldg(rows + e);
        int pos = atomicAdd(&g_work[r], 1);
        unsigned long long packed =
            (unsigned long long)(unsigned int)__ldg(cols + e) |
            ((unsigned long long)__float_as_uint(__ldg(vals + e)) << 32);
        g_edges[pos] = packed;
    }
}

// ---------------------------------------------------------------------------
// Pull-based CSR SPMM from fp16 source, fp32 accumulation.
// F=128: one warp/row, 4 halves (8B) per lane.
// ---------------------------------------------------------------------------
__global__ __launch_bounds__(256) void csr_spmm128_kernel(const __half* __restrict__ src,
                                                          float* __restrict__ dst,
                                                          int n_nodes) {
    const int lane = threadIdx.x & 31;
    const int row = (blockIdx.x * 256 + threadIdx.x) >> 5;
    if (row >= n_nodes) return;
    const int p0 = __ldg(&g_ptr[row]);
    const int p1 = __ldg(&g_ptr[row + 1]);
    const uint2* s8 = reinterpret_cast<const uint2*>(src);  // 4 halves per uint2, 32/row

    float4 acc = make_float4(0.f, 0.f, 0.f, 0.f);
    int e = p0;
    for (; e + 2 <= p1; e += 2) {
        unsigned long long e0 = __ldg(&g_edges[e]);
        unsigned long long e1 = __ldg(&g_edges[e + 1]);
        int c0 = (int)(unsigned int)e0;
        int c1 = (int)(unsigned int)e1;
        float v0 = __uint_as_float((unsigned int)(e0 >> 32));
        float v1 = __uint_as_float((unsigned int)(e1 >> 32));
        uint2 a = __ldg(s8 + (size_t)c0 * 32 + lane);
        uint2 b = __ldg(s8 + (size_t)c1 * 32 + lane);
        float2 a01 = __half22float2(*reinterpret_cast<__half2*>(&a.x));
        float2 a23 = __half22float2(*reinterpret_cast<__half2*>(&a.y));
        float2 b01 = __half22float2(*reinterpret_cast<__half2*>(&b.x));
        float2 b23 = __half22float2(*reinterpret_cast<__half2*>(&b.y));
        acc.x = fmaf(a01.x, v0, fmaf(b01.x, v1, acc.x));
        acc.y = fmaf(a01.y, v0, fmaf(b01.y, v1, acc.y));
        acc.z = fmaf(a23.x, v0, fmaf(b23.x, v1, acc.z));
        acc.w = fmaf(a23.y, v0, fmaf(b23.y, v1, acc.w));
    }
    if (e < p1) {
        unsigned long long e0 = __ldg(&g_edges[e]);
        int c0 = (int)(unsigned int)e0;
        float v0 = __uint_as_float((unsigned int)(e0 >> 32));
        uint2 a = __ldg(s8 + (size_t)c0 * 32 + lane);
        float2 a01 = __half22float2(*reinterpret_cast<__half2*>(&a.x));
        float2 a23 = __half22float2(*reinterpret_cast<__half2*>(&a.y));
        acc.x = fmaf(a01.x, v0, acc.x);
        acc.y = fmaf(a01.y, v0, acc.y);
        acc.z = fmaf(a23.x, v0, acc.z);
        acc.w = fmaf(a23.y, v0, acc.w);
    }
    reinterpret_cast<float4*>(dst)[(size_t)row * 32 + lane] = acc;
}

// F=64 fp16 source, fp32 out = sum + b2. 2 halves (4B) per lane.
__global__ __launch_bounds__(256) void csr_spmm64_kernel(const __half* __restrict__ src,
                                                         const float* __restrict__ b2,
                                                         float* __restrict__ dst,
                                                         int n_nodes) {
    const int lane = threadIdx.x & 31;
    const int row = (blockIdx.x * 256 + threadIdx.x) >> 5;
    if (row >= n_nodes) return;
    const int p0 = __ldg(&g_ptr[row]);
    const int p1 = __ldg(&g_ptr[row + 1]);
    const unsigned* s4 = reinterpret_cast<const unsigned*>(src);  // 2 halves, 32/row

    float2 acc = make_float2(0.f, 0.f);
    int e = p0;
    for (; e + 2 <= p1; e += 2) {
        unsigned long long e0 = __ldg(&g_edges[e]);
        unsigned long long e1 = __ldg(&g_edges[e + 1]);
        int c0 = (int)(unsigned int)e0;
        int c1 = (int)(unsigned int)e1;
        float v0 = __uint_as_float((unsigned int)(e0 >> 32));
        float v1 = __uint_as_float((unsigned int)(e1 >> 32));
        unsigned a = __ldg(s4 + (size_t)c0 * 32 + lane);
        unsigned b = __ldg(s4 + (size_t)c1 * 32 + lane);
        float2 af = __half22float2(*reinterpret_cast<__half2*>(&a));
        float2 bf = __half22float2(*reinterpret_cast<__half2*>(&b));
        acc.x = fmaf(af.x, v0, fmaf(bf.x, v1, acc.x));
        acc.y = fmaf(af.y, v0, fmaf(bf.y, v1, acc.y));
    }
    if (e < p1) {
        unsigned long long e0 = __ldg(&g_edges[e]);
        int c0 = (int)(unsigned int)e0;
        float v0 = __uint_as_float((unsigned int)(e0 >> 32));
        unsigned a = __ldg(s4 + (size_t)c0 * 32 + lane);
        float2 af = __half22float2(*reinterpret_cast<__half2*>(&a));
        acc.x = fmaf(af.x, v0, acc.x);
        acc.y = fmaf(af.y, v0, acc.y);
    }
    float2 bv = __ldg(reinterpret_cast<const float2*>(b2) + lane);
    acc.x += bv.x;
    acc.y += bv.y;
    reinterpret_cast<float2*>(dst)[(size_t)row * 32 + lane] = acc;
}

// ---------------------------------------------------------------------------
// GEMM: Yh[n_rows, N] (fp16) = A'[n_rows, K] @ W[K, N], fp32 math.
// A' = relu(A + bias) when RELU_BIAS. As padded to 68-float stride so each
// thread's RT-row strip is read with LDS.128 (warp-broadcast).
// ---------------------------------------------------------------------------
template <int K, int N, bool RELU_BIAS>
__global__ __launch_bounds__(256) void gemm_kernel(const float* __restrict__ A,
                                                   const float* __restrict__ W,
                                                   const float* __restrict__ bias,
                                                   __half* __restrict__ Yh,
                                                   int n_rows) {
    constexpr int KC = 16;
    constexpr int CT = N / 4;          // threads across cols (float4 of W each)
    constexpr int GROUPS = 256 / CT;   // row groups
    constexpr int RT = 64 / GROUPS;    // rows per thread (8 for N=128, 4 for N=64)

    __shared__ float As[KC][68];       // stride 272B: 16B-aligned rows
    __shared__ float Ws[KC][N];

    const int t = threadIdx.x;
    const int row0 = blockIdx.x * 64;
    const int tc = t % CT;
    const int tg = t / CT;

    float acc[RT][4];
#pragma unroll
    for (int r = 0; r < RT; r++) {
        acc[r][0] = 0.f; acc[r][1] = 0.f; acc[r][2] = 0.f; acc[r][3] = 0.f;
    }

    for (int k0 = 0; k0 < K; k0 += KC) {
        {
            const int r = t >> 2;
            const int kq = (t & 3) * 4;
            const int grow = row0 + r;
            float4 av = make_float4(0.f, 0.f, 0.f, 0.f);
            if (grow < n_rows)
                av = *reinterpret_cast<const float4*>(A + (size_t)grow * K + k0 + kq);
            if (RELU_BIAS) {
                float4 bv = *reinterpret_cast<const float4*>(bias + k0 + kq);
                av.x = fmaxf(av.x + bv.x, 0.f);
                av.y = fmaxf(av.y + bv.y, 0.f);
                av.z = fmaxf(av.z + bv.z, 0.f);
                av.w = fmaxf(av.w + bv.w, 0.f);
            }
            As[kq + 0][r] = av.x;
            As[kq + 1][r] = av.y;
            As[kq + 2][r] = av.z;
            As[kq + 3][r] = av.w;
        }
        {
            constexpr int VEC = KC * N / 4;
#pragma unroll
            for (int j = 0; j < VEC / 256; j++) {
                int idx = t + 256 * j;
                int kk = idx / (N / 4);
                int nq = idx % (N / 4);
                *reinterpret_cast<float4*>(&Ws[kk][nq * 4]) =
                    *reinterpret_cast<const float4*>(W + (size_t)(k0 + kk) * N + nq * 4);
            }
        }
        __syncthreads();

#pragma unroll
        for (int k = 0; k < KC; k++) {
            float4 wv = *reinterpret_cast<float4*>(&Ws[k][tc * 4]);
            const float4* asv = reinterpret_cast<const float4*>(&As[k][tg * RT]);
#pragma unroll
            for (int q = 0; q < RT / 4; q++) {
                float4 a4 = asv[q];
                float av[4] = {a4.x, a4.y, a4.z, a4.w};
#pragma unroll
                for (int j = 0; j < 4; j++) {
                    int r = q * 4 + j;
                    acc[r][0] += av[j] * wv.x;
                    acc[r][1] += av[j] * wv.y;
                    acc[r][2] += av[j] * wv.z;
                    acc[r][3] += av[j] * wv.w;
                }
            }
        }
        __syncthreads();
    }

#pragma unroll
    for (int r = 0; r < RT; r++) {
        int grow = row0 + tg * RT + r;
        if (grow < n_rows) {
            __half2 p0 = __float22half2_rn(make_float2(acc[r][0], acc[r][1]));
            __half2 p1 = __float22half2_rn(make_float2(acc[r][2], acc[r][3]));
            uint2 o;
            o.x = *reinterpret_cast<unsigned*>(&p0);
            o.y = *reinterpret_cast<unsigned*>(&p1);
            *reinterpret_cast<uint2*>(Yh + (size_t)grow * N + tc * 4) = o;
        }
    }
}

// ---------------------------------------------------------------------------
// launch
// ---------------------------------------------------------------------------
extern "C" void kernel_launch(void* const* d_in, const int* in_sizes, int n_in,
                              void* d_out, int out_size) {
    const float* x = (const float*)d_in[0];
    const int* adj_rows = (const int*)d_in[1];
    const int* adj_cols = (const int*)d_in[2];
    const float* adj_vals = (const float*)d_in[3];
    const float* W1 = (const float*)d_in[4];
    const float* b1 = (const float*)d_in[5];
    const float* W2 = (const float*)d_in[6];
    const float* b2 = (const float*)d_in[7];
    float* out = (float*)d_out;

    const int n_nodes = in_sizes[0] / 256;
    const int n_edges = in_sizes[1];

    void* yp_ = nullptr;
    void* hp_ = nullptr;
    cudaGetSymbolAddress(&yp_, g_y);
    cudaGetSymbolAddress(&hp_, g_h);
    __half* y = (__half*)yp_;
    float* h = (float*)hp_;
    __half* z = y;  // reuse g_y (fp16) for z after spmm1 consumed y

    const int nb_scan = (n_nodes + 1023) / 1024;
    const int eb = (n_edges + 255) / 256;
    const int nb_nodes = (n_nodes + 255) / 256;

    // --- CSR build ---
    zero_cnt_kernel<<<nb_nodes, 256>>>(n_nodes);
    hist_kernel<<<eb, 256>>>(adj_rows, n_edges);
    scan1_kernel<<<nb_scan, 256>>>(n_nodes);
    scan2_kernel<<<1, 256>>>(nb_scan);
    scan3_kernel<<<nb_nodes + 1, 256>>>(n_nodes, n_edges);
    scatter_kernel<<<eb, 256>>>(adj_rows, adj_cols, adj_vals, n_edges);

    // --- y = fp16(x @ W1) ---
    gemm_kernel<256, F1, false><<<(n_nodes + 63) / 64, 256>>>(x, W1, nullptr, y, n_nodes);
    // --- h = spmm(y) (fp32 accum) ---
    csr_spmm128_kernel<<<(n_nodes * 32 + 255) / 256, 256>>>(y, h, n_nodes);
    // --- z = fp16(relu(h + b1) @ W2) ---
    gemm_kernel<F1, F2, true><<<(n_nodes + 63) / 64, 256>>>(h, W2, b1, z, n_nodes);
    // --- out = spmm(z) + b2 ---
    csr_spmm64_kernel<<<(n_nodes * 32 + 255) / 256, 256>>>(z, b2, out, n_nodes);
}

// round 8
// speedup vs baseline: 2.5968x; 1.4694x over previous
#include <cuda_runtime.h>
#include <cuda_fp16.h>
#include <mma.h>
#include <cstdint>

using namespace nvcuda;

#define F1 128
#define F2 64
#define MAX_NODES 100000
#define MAX_EDGES 3200000

// ---------------------------------------------------------------------------
// Device-global scratch (allocation-free per harness rules)
// g_y: fp16 x@W1 [N,128]; later reused for fp16 z [N,64]
// g_h: fp32 spmm1 output [N,128]
// ---------------------------------------------------------------------------
__device__ __half g_y[(size_t)MAX_NODES * F1];
__device__ float g_h[(size_t)MAX_NODES * F1];
__device__ unsigned long long g_edges[MAX_EDGES]; // packed (col, val) sorted by row
__device__ int g_cnt[MAX_NODES];
__device__ int g_ptrE[MAX_NODES];
__device__ int g_bsum[128];
__device__ int g_bsumE[128];
__device__ int g_ptr[MAX_NODES + 1];
__device__ int g_work[MAX_NODES];

// ---------------------------------------------------------------------------
// CSR build: zero counts -> histogram -> 2-level exclusive scan -> scatter
// ---------------------------------------------------------------------------
__global__ __launch_bounds__(256) void zero_cnt_kernel(int n_nodes) {
    int i = blockIdx.x * 256 + threadIdx.x;
    if (i < n_nodes) g_cnt[i] = 0;
}

__global__ __launch_bounds__(256) void hist_kernel(const int* __restrict__ rows,
                                                   int n_edges) {
    int e = blockIdx.x * 256 + threadIdx.x;
    if (e < n_edges) atomicAdd(&g_cnt[__ldg(rows + e)], 1);
}

__global__ __launch_bounds__(256) void scan1_kernel(int n) {
    __shared__ int s[256];
    const int t = threadIdx.x;
    const int base = blockIdx.x * 1024 + t * 4;
    int v[4];
#pragma unroll
    for (int j = 0; j < 4; j++) v[j] = (base + j < n) ? g_cnt[base + j] : 0;
    int tsum = v[0] + v[1] + v[2] + v[3];
    s[t] = tsum;
    __syncthreads();
    for (int off = 1; off < 256; off <<= 1) {
        int x = 0;
        if (t >= off) x = s[t - off];
        __syncthreads();
        if (t >= off) s[t] += x;
        __syncthreads();
    }
    int run = s[t] - tsum;
#pragma unroll
    for (int j = 0; j < 4; j++) {
        if (base + j < n) g_ptrE[base + j] = run;
        run += v[j];
    }
    if (t == 255) g_bsum[blockIdx.x] = s[255];
}

__global__ __launch_bounds__(256) void scan2_kernel(int nb) {
    __shared__ int s[256];
    const int t = threadIdx.x;
    const int base = t * 4;
    int v[4];
#pragma unroll
    for (int j = 0; j < 4; j++) v[j] = (base + j < nb) ? g_bsum[base + j] : 0;
    int tsum = v[0] + v[1] + v[2] + v[3];
    s[t] = tsum;
    __syncthreads();
    for (int off = 1; off < 256; off <<= 1) {
        int x = 0;
        if (t >= off) x = s[t - off];
        __syncthreads();
        if (t >= off) s[t] += x;
        __syncthreads();
    }
    int run = s[t] - tsum;
#pragma unroll
    for (int j = 0; j < 4; j++) {
        if (base + j < nb) g_bsumE[base + j] = run;
        run += v[j];
    }
}

__global__ __launch_bounds__(256) void scan3_kernel(int n_nodes, int n_edges) {
    int i = blockIdx.x * 256 + threadIdx.x;
    if (i < n_nodes) {
        int p = g_ptrE[i] + g_bsumE[i >> 10];
        g_ptr[i] = p;
        g_work[i] = p;
    }
    if (i == 0) g_ptr[n_nodes] = n_edges;
}

__global__ __launch_bounds__(256) void scatter_kernel(const int* __restrict__ rows,
                                                      const int* __restrict__ cols,
                                                      const float* __restrict__ vals,
                                                      int n_edges) {
    int e = blockIdx.x * 256 + threadIdx.x;
    if (e < n_edges) {
        int r = __ldg(rows + e);
        int pos = atomicAdd(&g_work[r], 1);
        unsigned long long packed =
            (unsigned long long)(unsigned int)__ldg(cols + e) |
            ((unsigned long long)__float_as_uint(__ldg(vals + e)) << 32);
        g_edges[pos] = packed;
    }
}

// ---------------------------------------------------------------------------
// Pull-based CSR SPMM from fp16 source, fp32 accumulation.
// ---------------------------------------------------------------------------
__global__ __launch_bounds__(256) void csr_spmm128_kernel(const __half* __restrict__ src,
                                                          float* __restrict__ dst,
                                                          int n_nodes) {
    const int lane = threadIdx.x & 31;
    const int row = (blockIdx.x * 256 + threadIdx.x) >> 5;
    if (row >= n_nodes) return;
    const int p0 = __ldg(&g_ptr[row]);
    const int p1 = __ldg(&g_ptr[row + 1]);
    const uint2* s8 = reinterpret_cast<const uint2*>(src);

    float4 acc = make_float4(0.f, 0.f, 0.f, 0.f);
    int e = p0;
    for (; e + 2 <= p1; e += 2) {
        unsigned long long e0 = __ldg(&g_edges[e]);
        unsigned long long e1 = __ldg(&g_edges[e + 1]);
        int c0 = (int)(unsigned int)e0;
        int c1 = (int)(unsigned int)e1;
        float v0 = __uint_as_float((unsigned int)(e0 >> 32));
        float v1 = __uint_as_float((unsigned int)(e1 >> 32));
        uint2 a = __ldg(s8 + (size_t)c0 * 32 + lane);
        uint2 b = __ldg(s8 + (size_t)c1 * 32 + lane);
        float2 a01 = __half22float2(*reinterpret_cast<__half2*>(&a.x));
        float2 a23 = __half22float2(*reinterpret_cast<__half2*>(&a.y));
        float2 b01 = __half22float2(*reinterpret_cast<__half2*>(&b.x));
        float2 b23 = __half22float2(*reinterpret_cast<__half2*>(&b.y));
        acc.x = fmaf(a01.x, v0, fmaf(b01.x, v1, acc.x));
        acc.y = fmaf(a01.y, v0, fmaf(b01.y, v1, acc.y));
        acc.z = fmaf(a23.x, v0, fmaf(b23.x, v1, acc.z));
        acc.w = fmaf(a23.y, v0, fmaf(b23.y, v1, acc.w));
    }
    if (e < p1) {
        unsigned long long e0 = __ldg(&g_edges[e]);
        int c0 = (int)(unsigned int)e0;
        float v0 = __uint_as_float((unsigned int)(e0 >> 32));
        uint2 a = __ldg(s8 + (size_t)c0 * 32 + lane);
        float2 a01 = __half22float2(*reinterpret_cast<__half2*>(&a.x));
        float2 a23 = __half22float2(*reinterpret_cast<__half2*>(&a.y));
        acc.x = fmaf(a01.x, v0, acc.x);
        acc.y = fmaf(a01.y, v0, acc.y);
        acc.z = fmaf(a23.x, v0, acc.z);
        acc.w = fmaf(a23.y, v0, acc.w);
    }
    reinterpret_cast<float4*>(dst)[(size_t)row * 32 + lane] = acc;
}

__global__ __launch_bounds__(256) void csr_spmm64_kernel(const __half* __restrict__ src,
                                                         const float* __restrict__ b2,
                                                         float* __restrict__ dst,
                                                         int n_nodes) {
    const int lane = threadIdx.x & 31;
    const int row = (blockIdx.x * 256 + threadIdx.x) >> 5;
    if (row >= n_nodes) return;
    const int p0 = __ldg(&g_ptr[row]);
    const int p1 = __ldg(&g_ptr[row + 1]);
    const unsigned* s4 = reinterpret_cast<const unsigned*>(src);

    float2 acc = make_float2(0.f, 0.f);
    int e = p0;
    for (; e + 2 <= p1; e += 2) {
        unsigned long long e0 = __ldg(&g_edges[e]);
        unsigned long long e1 = __ldg(&g_edges[e + 1]);
        int c0 = (int)(unsigned int)e0;
        int c1 = (int)(unsigned int)e1;
        float v0 = __uint_as_float((unsigned int)(e0 >> 32));
        float v1 = __uint_as_float((unsigned int)(e1 >> 32));
        unsigned a = __ldg(s4 + (size_t)c0 * 32 + lane);
        unsigned b = __ldg(s4 + (size_t)c1 * 32 + lane);
        float2 af = __half22float2(*reinterpret_cast<__half2*>(&a));
        float2 bf = __half22float2(*reinterpret_cast<__half2*>(&b));
        acc.x = fmaf(af.x, v0, fmaf(bf.x, v1, acc.x));
        acc.y = fmaf(af.y, v0, fmaf(bf.y, v1, acc.y));
    }
    if (e < p1) {
        unsigned long long e0 = __ldg(&g_edges[e]);
        int c0 = (int)(unsigned int)e0;
        float v0 = __uint_as_float((unsigned int)(e0 >> 32));
        unsigned a = __ldg(s4 + (size_t)c0 * 32 + lane);
        float2 af = __half22float2(*reinterpret_cast<__half2*>(&a));
        acc.x = fmaf(af.x, v0, acc.x);
        acc.y = fmaf(af.y, v0, acc.y);
    }
    float2 bv = __ldg(reinterpret_cast<const float2*>(b2) + lane);
    acc.x += bv.x;
    acc.y += bv.y;
    reinterpret_cast<float2*>(dst)[(size_t)row * 32 + lane] = acc;
}

// ---------------------------------------------------------------------------
// Tensor-core GEMM (wmma m16n16k16, fp16 in / fp32 acc):
//   Yh[n_rows, N] (fp16) = A'[n_rows, K] @ W[K, N]
//   A' = A, or relu(A + bias) when RELU_BIAS (fused into fp32->fp16 staging).
// Tile: BM=128, BK=64, BN=N. 8 warps; warp tile 32 x (BN/2).
// ---------------------------------------------------------------------------
template <int K, int N, bool RELU_BIAS>
__global__ __launch_bounds__(256) void wmma_gemm_kernel(const float* __restrict__ A,
                                                        const float* __restrict__ W,
                                                        const float* __restrict__ bias,
                                                        __half* __restrict__ Yh,
                                                        int n_rows) {
    constexpr int BM = 128;
    constexpr int BK = 64;
    constexpr int BN = N;
    constexpr int LDA = BK + 8;   // 72 halves (144B rows, 16B aligned)
    constexpr int LDB = BN + 8;   // 136 or 72 halves
    constexpr int WN = BN / 32;   // wmma frags along N per warp (4 or 2)
    constexpr int WM = 2;         // 2 x 16 = 32 rows per warp

    __shared__ __half As[BM][LDA];
    __shared__ __half Bs[BK][LDB];
    __shared__ float St[8][16][20];

    const int t = threadIdx.x;
    const int warp = t >> 5;
    const int lane = t & 31;
    const int row0 = blockIdx.x * BM;
    const int warpM = warp & 3;        // 0..3 (32 rows each)
    const int warpN = warp >> 2;       // 0..1 (BN/2 cols each)

    wmma::fragment<wmma::accumulator, 16, 16, 16, float> acc[WM][WN];
#pragma unroll
    for (int mi = 0; mi < WM; mi++)
#pragma unroll
        for (int ni = 0; ni < WN; ni++) wmma::fill_fragment(acc[mi][ni], 0.0f);

    for (int k0 = 0; k0 < K; k0 += BK) {
        // --- stage A tile [BM x BK], fp32 -> fp16 (+bias+relu) ---
        {
            const int quad = t & 15;        // 16 quads cover 64 cols
            const int rsub = t >> 4;        // 0..15
#pragma unroll
            for (int p = 0; p < BM / 16; p++) {
                const int row = p * 16 + rsub;
                const int grow = row0 + row;
                float4 av = make_float4(0.f, 0.f, 0.f, 0.f);
                if (grow < n_rows)
                    av = *reinterpret_cast<const float4*>(A + (size_t)grow * K + k0 + quad * 4);
                if (RELU_BIAS) {
                    float4 bv = *reinterpret_cast<const float4*>(bias + k0 + quad * 4);
                    av.x = fmaxf(av.x + bv.x, 0.f);
                    av.y = fmaxf(av.y + bv.y, 0.f);
                    av.z = fmaxf(av.z + bv.z, 0.f);
                    av.w = fmaxf(av.w + bv.w, 0.f);
                }
                __half2 h01 = __float22half2_rn(make_float2(av.x, av.y));
                __half2 h23 = __float22half2_rn(make_float2(av.z, av.w));
                uint2 o;
                o.x = *reinterpret_cast<unsigned*>(&h01);
                o.y = *reinterpret_cast<unsigned*>(&h23);
                *reinterpret_cast<uint2*>(&As[row][quad * 4]) = o;
            }
        }
        // --- stage B tile [BK x BN], fp32 -> fp16 ---
        {
            constexpr int QPR = BN / 4;            // float4 per row
            constexpr int RPP = 256 / QPR;         // rows per pass
            const int quad = t % QPR;
            const int rsub = t / QPR;
#pragma unroll
            for (int p = 0; p < BK / RPP; p++) {
                const int row = p * RPP + rsub;
                float4 wv = *reinterpret_cast<const float4*>(W + (size_t)(k0 + row) * BN + quad * 4);
                __half2 h01 = __float22half2_rn(make_float2(wv.x, wv.y));
                __half2 h23 = __float22half2_rn(make_float2(wv.z, wv.w));
                uint2 o;
                o.x = *reinterpret_cast<unsigned*>(&h01);
                o.y = *reinterpret_cast<unsigned*>(&h23);
                *reinterpret_cast<uint2*>(&Bs[row][quad * 4]) = o;
            }
        }
        __syncthreads();

#pragma unroll
        for (int kk = 0; kk < BK; kk += 16) {
            wmma::fragment<wmma::matrix_a, 16, 16, 16, __half, wmma::row_major> af[WM];
            wmma::fragment<wmma::matrix_b, 16, 16, 16, __half, wmma::row_major> bf[WN];
#pragma unroll
            for (int mi = 0; mi < WM; mi++)
                wmma::load_matrix_sync(af[mi], &As[warpM * 32 + mi * 16][kk], LDA);
#pragma unroll
            for (int ni = 0; ni < WN; ni++)
                wmma::load_matrix_sync(bf[ni], &Bs[kk][warpN * (BN / 2) + ni * 16], LDB);
#pragma unroll
            for (int mi = 0; mi < WM; mi++)
#pragma unroll
                for (int ni = 0; ni < WN; ni++)
                    wmma::mma_sync(acc[mi][ni], af[mi], bf[ni], acc[mi][ni]);
        }
        __syncthreads();
    }

    // --- epilogue: fp32 frag -> per-warp smem -> fp16 gmem ---
#pragma unroll
    for (int mi = 0; mi < WM; mi++) {
#pragma unroll
        for (int ni = 0; ni < WN; ni++) {
            wmma::store_matrix_sync(&St[warp][0][0], acc[mi][ni], 20, wmma::mem_row_major);
            __syncwarp();
            const int r = lane >> 1;
            const int cq = (lane & 1) * 8;
            const int grow = row0 + warpM * 32 + mi * 16 + r;
            if (grow < n_rows) {
                float* sp = &St[warp][r][cq];
                __half2 h0 = __float22half2_rn(make_float2(sp[0], sp[1]));
                __half2 h1 = __float22half2_rn(make_float2(sp[2], sp[3]));
                __half2 h2 = __float22half2_rn(make_float2(sp[4], sp[5]));
                __half2 h3 = __float22half2_rn(make_float2(sp[6], sp[7]));
                uint4 o;
                o.x = *reinterpret_cast<unsigned*>(&h0);
                o.y = *reinterpret_cast<unsigned*>(&h1);
                o.z = *reinterpret_cast<unsigned*>(&h2);
                o.w = *reinterpret_cast<unsigned*>(&h3);
                const int gcol = warpN * (BN / 2) + ni * 16 + cq;
                *reinterpret_cast<uint4*>(Yh + (size_t)grow * N + gcol) = o;
            }
            __syncwarp();
        }
    }
}

// ---------------------------------------------------------------------------
// launch
// ---------------------------------------------------------------------------
extern "C" void kernel_launch(void* const* d_in, const int* in_sizes, int n_in,
                              void* d_out, int out_size) {
    const float* x = (const float*)d_in[0];
    const int* adj_rows = (const int*)d_in[1];
    const int* adj_cols = (const int*)d_in[2];
    const float* adj_vals = (const float*)d_in[3];
    const float* W1 = (const float*)d_in[4];
    const float* b1 = (const float*)d_in[5];
    const float* W2 = (const float*)d_in[6];
    const float* b2 = (const float*)d_in[7];
    float* out = (float*)d_out;

    const int n_nodes = in_sizes[0] / 256;
    const int n_edges = in_sizes[1];

    void* yp_ = nullptr;
    void* hp_ = nullptr;
    cudaGetSymbolAddress(&yp_, g_y);
    cudaGetSymbolAddress(&hp_, g_h);
    __half* y = (__half*)yp_;
    float* h = (float*)hp_;
    __half* z = y;  // reuse g_y (fp16) for z after spmm1 consumed y

    const int nb_scan = (n_nodes + 1023) / 1024;
    const int eb = (n_edges + 255) / 256;
    const int nb_nodes = (n_nodes + 255) / 256;

    // --- CSR build ---
    zero_cnt_kernel<<<nb_nodes, 256>>>(n_nodes);
    hist_kernel<<<eb, 256>>>(adj_rows, n_edges);
    scan1_kernel<<<nb_scan, 256>>>(n_nodes);
    scan2_kernel<<<1, 256>>>(nb_scan);
    scan3_kernel<<<nb_nodes + 1, 256>>>(n_nodes, n_edges);
    scatter_kernel<<<eb, 256>>>(adj_rows, adj_cols, adj_vals, n_edges);

    // --- y = fp16(x @ W1)  [tensor cores] ---
    wmma_gemm_kernel<256, F1, false><<<(n_nodes + 127) / 128, 256>>>(x, W1, nullptr, y, n_nodes);
    // --- h = spmm(y) (fp32 accum) ---
    csr_spmm128_kernel<<<(n_nodes * 32 + 255) / 256, 256>>>(y, h, n_nodes);
    // --- z = fp16(relu(h + b1) @ W2)  [tensor cores] ---
    wmma_gemm_kernel<F1, F2, true><<<(n_nodes + 127) / 128, 256>>>(h, W2, b1, z, n_nodes);
    // --- out = spmm(z) + b2 ---
    csr_spmm64_kernel<<<(n_nodes * 32 + 255) / 256, 256>>>(z, b2, out, n_nodes);
}